// round 15
// baseline (speedup 1.0000x reference)
#include <cuda_runtime.h>
#include <cstdint>
#include <math.h>

#define BB 2048
#define NN 200
#define HH 128
#define TT 180
#define NGRP 256          // producer groups, 8 batches each

__device__ float g_V0[BB * HH];   // V0[b] = W^T (W x[b,0] + bias)
__device__ int   g_flag[NGRP];    // zero-init; set stays benign across replays

__device__ __forceinline__ float neg_inf() { return __int_as_float(0xff800000); }

__global__ void __launch_bounds__(256, 4)
k_route(const float* __restrict__ x, const float* __restrict__ W,
        const float* __restrict__ bias, const float* __restrict__ coords,
        const float* __restrict__ demands, const float* __restrict__ capacity,
        const int* __restrict__ nsteps, float* __restrict__ out, int out_size) {
    __shared__ float buf[2048];                  // 8KB union
    // ---- route-phase aliases ----
    float* cx   = buf;            float* cy    = buf + 200;
    float* dem  = buf + 400;      int*   vis   = (int*)(buf + 600);
    float* vsm  = buf + 800;      float* vpart = buf + 928;
    float* qsm  = buf + 1056;     float* xrow  = buf + 1184;
    float* red  = buf + 1312;     int*   redi  = (int*)(buf + 1344);
    int*   nxtp = (int*)(buf + 1376);
    // ---- producer-phase aliases (dead before route arrays are written) ----
    float* xs = buf;              // [8][128]
    float* qs = buf + 1024;       // [8][128]

    const int tid  = threadIdx.x;
    const int b    = blockIdx.x;
    const int lane = tid & 31;
    const int wid  = tid >> 5;
    const int T    = nsteps ? nsteps[0] : TT;

    // ====== producers: CTA g computes V0 for batches 8g..8g+7 ================
    if (b < NGRP) {
        const int gb0 = b * 8;
        {   // stage x0 rows: one float4 per thread
            int r = tid >> 5, jj = tid & 31;
            *(float4*)(xs + r * HH + jj * 4) =
                *(const float4*)(x + (size_t)(gb0 + r) * NN * HH + jj * 4);
        }
        __syncthreads();
        {   // phase 1: q[j][o] = W[o,:]·x0[j] + bias[o]
            const int o = tid & 127, jb = (tid >> 7) * 4;
            float acc[4];
            float bo = bias[o];
            #pragma unroll
            for (int jj = 0; jj < 4; jj++) acc[jj] = bo;
            for (int h = 0; h < HH; h += 4) {
                float4 w4 = *(const float4*)(W + (size_t)o * HH + h);
                #pragma unroll
                for (int jj = 0; jj < 4; jj++) {
                    float4 xv = *(const float4*)(xs + (jb + jj) * HH + h);
                    acc[jj] = fmaf(w4.x, xv.x, fmaf(w4.y, xv.y,
                              fmaf(w4.z, xv.z, fmaf(w4.w, xv.w, acc[jj]))));
                }
            }
            #pragma unroll
            for (int jj = 0; jj < 4; jj++) qs[(jb + jj) * HH + o] = acc[jj];
        }
        __syncthreads();
        {   // phase 2: V0[j][h] = sum_o W[o][h] q[j][o]
            const int h = tid & 127, jb = (tid >> 7) * 4;
            float acc[4];
            #pragma unroll
            for (int jj = 0; jj < 4; jj++) acc[jj] = 0.f;
            #pragma unroll 4
            for (int o = 0; o < HH; o++) {
                float w = W[(size_t)o * HH + h];
                #pragma unroll
                for (int jj = 0; jj < 4; jj++)
                    acc[jj] = fmaf(w, qs[(jb + jj) * HH + o], acc[jj]);
            }
            #pragma unroll
            for (int jj = 0; jj < 4; jj++)
                g_V0[(size_t)(gb0 + jb + jj) * HH + h] = acc[jj];
        }
        __threadfence();
        __syncthreads();
        if (tid == 0) atomicExch(&g_flag[b], 1);
    }

    // ====== prologue (overlaps with producers) ===============================
    if (tid < T) out[(size_t)b * T + tid] = 0.0f;        // own action row
    {
        long long tail = (long long)out_size - (long long)BB * T;
        if (tail > 0) {                                   // share of log_probs tail
            int chunk = (int)((tail + BB - 1) / BB);
            long long s0 = (long long)BB * T + (long long)b * chunk;
            for (int i = tid; i < chunk; i += 256) {
                long long idx = s0 + i;
                if (idx < out_size) out[idx] = 0.0f;
            }
        }
    }
    __syncthreads();                                      // producer scratch dead
    {
        const float2* cb2 = (const float2*)(coords + (size_t)b * NN * 2);
        const float*  db  = demands + (size_t)b * NN;
        if (tid < NN) {
            float2 c2 = cb2[tid];
            cx[tid] = c2.x; cy[tid] = c2.y;
            dem[tid] = db[tid];
            vis[tid] = 0;
        }
    }
    // wait for this batch's V0 (producers all resident in wave 1: no deadlock)
    if (tid == 0) {
        while (atomicAdd(&g_flag[b >> 3], 0) == 0) __nanosleep(64);
        __threadfence();
    }
    __syncthreads();
    if (tid < HH) vsm[tid] = g_V0[(size_t)b * HH + tid];
    __syncthreads();

    // ====== routing: thread-per-node, shuffle-free stream ====================
    const float cap = capacity[b];
    float rem = cap;
    int cur = 0;
    const float* xb = x + (size_t)b * NN * HH;

    float myd = 0.f, mycx = 0.f, mycy = 0.f;
    if (tid < NN) { myd = dem[tid]; mycx = cx[tid]; mycy = cy[tid]; }

    for (int step = 0; step < T; step++) {
        float s = neg_inf();
        if (tid < NN) {
            const float* xr = xb + (size_t)tid * HH;
            float a0 = 0.f, a1 = 0.f, a2 = 0.f, a3 = 0.f;
            #pragma unroll
            for (int h = 0; h < HH; h += 16) {
                float4 x0 = *(const float4*)(xr + h);
                float4 x1 = *(const float4*)(xr + h + 4);
                float4 x2 = *(const float4*)(xr + h + 8);
                float4 x3 = *(const float4*)(xr + h + 12);
                float4 v0 = *(const float4*)(vsm + h);
                float4 v1 = *(const float4*)(vsm + h + 4);
                float4 v2 = *(const float4*)(vsm + h + 8);
                float4 v3 = *(const float4*)(vsm + h + 12);
                a0 = fmaf(x0.x, v0.x, fmaf(x0.y, v0.y, fmaf(x0.z, v0.z, fmaf(x0.w, v0.w, a0))));
                a1 = fmaf(x1.x, v1.x, fmaf(x1.y, v1.y, fmaf(x1.z, v1.z, fmaf(x1.w, v1.w, a1))));
                a2 = fmaf(x2.x, v2.x, fmaf(x2.y, v2.y, fmaf(x2.z, v2.z, fmaf(x2.w, v2.w, a2))));
                a3 = fmaf(x3.x, v3.x, fmaf(x3.y, v3.y, fmaf(x3.z, v3.z, fmaf(x3.w, v3.w, a3))));
            }
            float sim = (a0 + a1) + (a2 + a3);
            float dx = mycx - cx[cur], dy = mycy - cy[cur];
            s = sim - 0.1f * sqrtf(dx * dx + dy * dy);
            if (tid != 0 && (vis[tid] || (myd > rem))) s = neg_inf();
        }
        // warp argmax with first-index tie-break, then cross-warp
        float bv = s; int bi = tid;
        #pragma unroll
        for (int off = 16; off > 0; off >>= 1) {
            float ov = __shfl_xor_sync(0xffffffffu, bv, off);
            int   oi = __shfl_xor_sync(0xffffffffu, bi, off);
            if (ov > bv || (ov == bv && oi < bi)) { bv = ov; bi = oi; }
        }
        if (lane == 0) { red[wid] = bv; redi[wid] = bi; }
        __syncthreads();
        if (tid == 0) {
            float Bv = red[0]; int Bi = redi[0];
            #pragma unroll
            for (int w = 1; w < 8; w++) {
                float v = red[w]; int i2 = redi[w];
                if (v > Bv || (v == Bv && i2 < Bi)) { Bv = v; Bi = i2; }
            }
            nxtp[0] = Bi;
            vis[Bi] = 1;
            out[(size_t)b * T + step] = (float)Bi;
        }
        __syncthreads();
        int nxt = nxtp[0];
        rem = (nxt == 0) ? cap : (rem - dem[nxt]);
        int prev = cur;
        cur = nxt;
        // depot fixed point: identical state recurs -> remaining actions all 0
        // (row already zeroed by this CTA). Exact, not approximate.
        if (prev == 0 && nxt == 0) break;

        // ---- live path (rare): v = W^T (W x_cur + bias) ---------------------
        if (tid < 32)
            *(float4*)(xrow + tid * 4) = *(const float4*)(xb + (size_t)cur * HH + tid * 4);
        __syncthreads();
        {   // q[o] = W[o,:]·xrow + bias[o], warp-per-row
            float4 xc = *(const float4*)(xrow + lane * 4);
            #pragma unroll
            for (int r = 0; r < 16; r++) {
                int o = wid + r * 8;
                float4 w4 = *(const float4*)(W + (size_t)o * HH + lane * 4);
                float p = fmaf(w4.x, xc.x, fmaf(w4.y, xc.y,
                          fmaf(w4.z, xc.z, w4.w * xc.w)));
                #pragma unroll
                for (int off = 16; off > 0; off >>= 1)
                    p += __shfl_xor_sync(0xffffffffu, p, off);
                if (lane == 0) qsm[o] = p + bias[o];
            }
        }
        __syncthreads();
        {   // v[h] = sum_o W[o][h] q[o], coalesced columns, o halved
            int h = tid & 127, half = tid >> 7;
            float acc = 0.f;
            const float* Wp = W + (size_t)(half * 64) * HH + h;
            const float* qp = qsm + half * 64;
            #pragma unroll 8
            for (int o = 0; o < 64; o++)
                acc = fmaf(Wp[(size_t)o * HH], qp[o], acc);
            if (half == 0) vsm[h] = acc; else vpart[h] = acc;
        }
        __syncthreads();
        if (tid < HH) vsm[tid] += vpart[tid];
        __syncthreads();
    }
}

extern "C" void kernel_launch(void* const* d_in, const int* in_sizes, int n_in,
                              void* d_out, int out_size) {
    const float* x        = (const float*)d_in[0];
    const float* W        = (const float*)d_in[1];
    const float* bias     = (const float*)d_in[2];
    const float* coords   = (const float*)d_in[3];
    const float* demands  = (const float*)d_in[4];
    const float* capacity = (const float*)d_in[5];
    const int*   nsteps   = (n_in > 6) ? (const int*)d_in[6] : nullptr;
    float* out = (float*)d_out;

    k_route<<<BB, 256>>>(x, W, bias, coords, demands, capacity, nsteps, out, out_size);
}

// round 16
// speedup vs baseline: 1.1857x; 1.1857x over previous
#include <cuda_runtime.h>
#include <cstdint>
#include <math.h>

#define BB 2048
#define NN 200
#define HH 128
#define TT 180
#define NGRP 256          // producer groups, 8 batches each
#define RS 132            // padded smem row stride (floats)
#define NCH 7             // 6*32 + 8 rows

__device__ float g_V0[BB * HH];   // V0[b] = W^T (W x[b,0] + bias)
__device__ int   g_flag[NGRP];    // zero-init; set stays benign across replays

__device__ __forceinline__ float neg_inf() { return __int_as_float(0xff800000); }

__device__ __forceinline__ void cpa16(float* dst, const float* src) {
    unsigned s = (unsigned)__cvta_generic_to_shared(dst);
    asm volatile("cp.async.cg.shared.global [%0], [%1], 16;" :: "r"(s), "l"(src) : "memory");
}

// issue one chunk (rows*32 16B packets) + commit. All threads participate.
__device__ __forceinline__ void issue_chunk(float* bufc, const float* src0, int rows, int tid) {
    for (int idx = tid; idx < rows * 32; idx += 256) {
        int row = idx >> 5, u = idx & 31;
        cpa16(bufc + row * RS + u * 4, src0 + (size_t)row * HH + u * 4);
    }
    asm volatile("cp.async.commit_group;" ::: "memory");
}

// ---- static smem layout (floats) ----
// BUF0 [32][132] = 4224 | BUF1 = 4224..8448 | aux 8448..9856
#define BUF0 0
#define BUF1 4224
#define AUX  8448
#define SMEM_FLOATS 9856

__global__ void __launch_bounds__(256, 5)
k_route(const float* __restrict__ x, const float* __restrict__ W,
        const float* __restrict__ bias, const float* __restrict__ coords,
        const float* __restrict__ demands, const float* __restrict__ capacity,
        const int* __restrict__ nsteps, float* __restrict__ out, int out_size) {
    __shared__ float smem[SMEM_FLOATS];
    float* cx   = smem + AUX;         float* cy    = smem + AUX + 200;
    float* dem  = smem + AUX + 400;   int*   vis   = (int*)(smem + AUX + 600);
    float* vsm  = smem + AUX + 800;   float* vpart = smem + AUX + 928;
    float* qsm  = smem + AUX + 1056;  float* xrow  = smem + AUX + 1184;
    float* red  = smem + AUX + 1312;  int*   redi  = (int*)(smem + AUX + 1344);
    int*   nxtp = (int*)(smem + AUX + 1376);
    // producer scratch overlays BUF1 (chunk1 issued after producer phase)
    float* xs = smem + BUF1;          float* qs = smem + BUF1 + 1024;

    const int tid  = threadIdx.x;
    const int b    = blockIdx.x;
    const int lane = tid & 31;
    const int wid  = tid >> 5;
    const int g    = lane >> 3;       // 8-lane group 0..3
    const int j    = lane & 7;        // lane-in-group
    const int T    = nsteps ? nsteps[0] : TT;
    const float* xb = x + (size_t)b * NN * HH;
    const bool is_prod = (b < NGRP);

    // ---- start the x stream immediately ------------------------------------
    issue_chunk(smem + BUF0, xb, 32, tid);                 // group 0 -> buf0
    if (!is_prod) issue_chunk(smem + BUF1, xb + 32 * HH, 32, tid);  // group 1

    // ====== producers: CTA p computes V0 for batches 8p..8p+7 ================
    if (is_prod) {
        const int gb0 = b * 8;
        {   // stage x0 rows
            int r = tid >> 5, jj = tid & 31;
            *(float4*)(xs + r * HH + jj * 4) =
                *(const float4*)(x + (size_t)(gb0 + r) * NN * HH + jj * 4);
        }
        __syncthreads();
        {   // phase 1: q[j][o] = W[o,:]·x0[j] + bias[o]
            const int o = tid & 127, jb = (tid >> 7) * 4;
            float acc[4];
            float bo = bias[o];
            #pragma unroll
            for (int jj = 0; jj < 4; jj++) acc[jj] = bo;
            for (int h = 0; h < HH; h += 4) {
                float4 w4 = *(const float4*)(W + (size_t)o * HH + h);
                #pragma unroll
                for (int jj = 0; jj < 4; jj++) {
                    float4 xv = *(const float4*)(xs + (jb + jj) * HH + h);
                    acc[jj] = fmaf(w4.x, xv.x, fmaf(w4.y, xv.y,
                              fmaf(w4.z, xv.z, fmaf(w4.w, xv.w, acc[jj]))));
                }
            }
            #pragma unroll
            for (int jj = 0; jj < 4; jj++) qs[(jb + jj) * HH + o] = acc[jj];
        }
        __syncthreads();
        {   // phase 2: V0[j][h] = sum_o W[o][h] q[j][o]
            const int h = tid & 127, jb = (tid >> 7) * 4;
            float acc[4];
            #pragma unroll
            for (int jj = 0; jj < 4; jj++) acc[jj] = 0.f;
            #pragma unroll 4
            for (int o = 0; o < HH; o++) {
                float w = W[(size_t)o * HH + h];
                #pragma unroll
                for (int jj = 0; jj < 4; jj++)
                    acc[jj] = fmaf(w, qs[(jb + jj) * HH + o], acc[jj]);
            }
            #pragma unroll
            for (int jj = 0; jj < 4; jj++)
                g_V0[(size_t)(gb0 + jb + jj) * HH + h] = acc[jj];
        }
        __threadfence();
        __syncthreads();
        if (tid == 0) atomicExch(&g_flag[b], 1);
        // scratch (BUF1) now dead -> start chunk 1
        issue_chunk(smem + BUF1, xb + 32 * HH, 32, tid);   // group 1
    }

    // ====== prologue (overlaps with in-flight stream) ========================
    if (tid < T) out[(size_t)b * T + tid] = 0.0f;          // own action row
    {
        long long tail = (long long)out_size - (long long)BB * T;
        if (tail > 0) {                                    // share of log_probs tail
            int chunk = (int)((tail + BB - 1) / BB);
            long long s0 = (long long)BB * T + (long long)b * chunk;
            for (int i = tid; i < chunk; i += 256) {
                long long idx = s0 + i;
                if (idx < out_size) out[idx] = 0.0f;
            }
        }
    }
    {
        const float2* cb2 = (const float2*)(coords + (size_t)b * NN * 2);
        const float*  db  = demands + (size_t)b * NN;
        if (tid < NN) {
            float2 c2 = cb2[tid];
            cx[tid] = c2.x; cy[tid] = c2.y;
            dem[tid] = db[tid];
            vis[tid] = 0;
        }
    }
    if (tid == 0) {                                        // wait for V0
        while (atomicAdd(&g_flag[b >> 3], 0) == 0) __nanosleep(64);
        __threadfence();
    }
    __syncthreads();
    if (tid < HH) vsm[tid] = g_V0[(size_t)b * HH + tid];
    __syncthreads();

    // ====== step 0: pipelined chunked scoring (cur = 0) ======================
    const float cap = capacity[b];
    float rem = cap;
    int cur = 0;

    {
        float4 vr0 = *(const float4*)(vsm +   0 + j * 4);
        float4 vr1 = *(const float4*)(vsm +  32 + j * 4);
        float4 vr2 = *(const float4*)(vsm +  64 + j * 4);
        float4 vr3 = *(const float4*)(vsm +  96 + j * 4);
        float cxc = cx[0], cyc = cy[0];
        const int nl = wid + 8 * g;                        // local row 0..31

        float best = neg_inf();
        int bidx = NN;
        for (int c = 0; c < NCH; c++) {
            if (c < NCH - 1) asm volatile("cp.async.wait_group 1;" ::: "memory");
            else             asm volatile("cp.async.wait_group 0;" ::: "memory");
            __syncthreads();
            const float* bufc = smem + ((c & 1) ? BUF1 : BUF0);
            int n = c * 32 + nl;
            bool valid = (n < NN);
            float p = 0.f;
            if (valid) {
                const float* xr = bufc + nl * RS + j * 4;
                float4 a0 = *(const float4*)(xr);
                float4 a1 = *(const float4*)(xr + 32);
                float4 a2 = *(const float4*)(xr + 64);
                float4 a3 = *(const float4*)(xr + 96);
                p = fmaf(a0.x, vr0.x, fmaf(a0.y, vr0.y, fmaf(a0.z, vr0.z, a0.w * vr0.w)));
                p = fmaf(a1.x, vr1.x, fmaf(a1.y, vr1.y, fmaf(a1.z, vr1.z, fmaf(a1.w, vr1.w, p))));
                p = fmaf(a2.x, vr2.x, fmaf(a2.y, vr2.y, fmaf(a2.z, vr2.z, fmaf(a2.w, vr2.w, p))));
                p = fmaf(a3.x, vr3.x, fmaf(a3.y, vr3.y, fmaf(a3.z, vr3.z, fmaf(a3.w, vr3.w, p))));
            }
            p += __shfl_xor_sync(0xffffffffu, p, 4);
            p += __shfl_xor_sync(0xffffffffu, p, 2);
            p += __shfl_xor_sync(0xffffffffu, p, 1);
            float s = neg_inf();
            if (valid) {
                float dx = cx[n] - cxc, dy = cy[n] - cyc;
                s = p - 0.1f * sqrtf(dx * dx + dy * dy);
                if (n != 0 && (vis[n] || (dem[n] > rem))) s = neg_inf();
            }
            if (s > best) { best = s; bidx = n; }          // ascending n: strict >
            __syncthreads();                                // buffer free for reuse
            if (c + 2 < NCH) {
                int rows = (c + 2 == NCH - 1) ? 8 : 32;
                issue_chunk(smem + ((c & 1) ? BUF1 : BUF0),
                            xb + (size_t)(c + 2) * 32 * HH, rows, tid);
            }
        }
        if (j == 0) { red[wid * 4 + g] = best; redi[wid * 4 + g] = bidx; }
        __syncthreads();
        if (wid == 0) {                                    // first-index argmax
            float bv = red[lane]; int bi = redi[lane];
            #pragma unroll
            for (int off = 16; off > 0; off >>= 1) {
                float ov = __shfl_xor_sync(0xffffffffu, bv, off);
                int   oi = __shfl_xor_sync(0xffffffffu, bi, off);
                if (ov > bv || (ov == bv && oi < bi)) { bv = ov; bi = oi; }
            }
            if (lane == 0) {
                nxtp[0] = bi;
                vis[bi] = 1;
                out[(size_t)b * T + 0] = (float)bi;
            }
        }
        __syncthreads();
    }
    int nxt = nxtp[0];
    // depot fixed point at step 0: state recurs -> all remaining actions 0
    // (row already zeroed by this CTA). Exact, not approximate.
    if (nxt == 0) return;
    rem = rem - dem[nxt];
    cur = nxt;

    // ====== live path (rare): steps 1..T-1, GMEM grouped stream ==============
    for (int step = 1; step < T; step++) {
        // ---- v = W^T (W x_cur + bias) ---------------------------------------
        if (tid < 32)
            *(float4*)(xrow + tid * 4) = *(const float4*)(xb + (size_t)cur * HH + tid * 4);
        __syncthreads();
        {   // q[o] = W[o,:]·xrow + bias[o], warp-per-row
            float4 xc = *(const float4*)(xrow + lane * 4);
            #pragma unroll
            for (int r = 0; r < 16; r++) {
                int o = wid + r * 8;
                float4 w4 = *(const float4*)(W + (size_t)o * HH + lane * 4);
                float p = fmaf(w4.x, xc.x, fmaf(w4.y, xc.y,
                          fmaf(w4.z, xc.z, w4.w * xc.w)));
                #pragma unroll
                for (int off = 16; off > 0; off >>= 1)
                    p += __shfl_xor_sync(0xffffffffu, p, off);
                if (lane == 0) qsm[o] = p + bias[o];
            }
        }
        __syncthreads();
        {   // v[h] = sum_o W[o][h] q[o]
            int h = tid & 127, half = tid >> 7;
            float acc = 0.f;
            const float* Wp = W + (size_t)(half * 64) * HH + h;
            const float* qp = qsm + half * 64;
            #pragma unroll 8
            for (int o = 0; o < 64; o++)
                acc = fmaf(Wp[(size_t)o * HH], qp[o], acc);
            if (half == 0) vsm[h] = acc; else vpart[h] = acc;
        }
        __syncthreads();
        if (tid < HH) vsm[tid] += vpart[tid];
        __syncthreads();

        // ---- grouped scoring from GMEM (R14) --------------------------------
        float4 vr0 = *(const float4*)(vsm +   0 + j * 4);
        float4 vr1 = *(const float4*)(vsm +  32 + j * 4);
        float4 vr2 = *(const float4*)(vsm +  64 + j * 4);
        float4 vr3 = *(const float4*)(vsm +  96 + j * 4);
        float cxc = cx[cur], cyc = cy[cur];
        const int nbase = wid + 8 * g;
        float best = neg_inf();
        int bidx = NN;
        #pragma unroll 7
        for (int k = 0; k < 7; k++) {
            int n = nbase + 32 * k;
            bool valid = (n < NN);
            float p = 0.f;
            if (valid) {
                const float* xr = xb + (size_t)n * HH + j * 4;
                float4 a0 = *(const float4*)(xr);
                float4 a1 = *(const float4*)(xr + 32);
                float4 a2 = *(const float4*)(xr + 64);
                float4 a3 = *(const float4*)(xr + 96);
                p = fmaf(a0.x, vr0.x, fmaf(a0.y, vr0.y, fmaf(a0.z, vr0.z, a0.w * vr0.w)));
                p = fmaf(a1.x, vr1.x, fmaf(a1.y, vr1.y, fmaf(a1.z, vr1.z, fmaf(a1.w, vr1.w, p))));
                p = fmaf(a2.x, vr2.x, fmaf(a2.y, vr2.y, fmaf(a2.z, vr2.z, fmaf(a2.w, vr2.w, p))));
                p = fmaf(a3.x, vr3.x, fmaf(a3.y, vr3.y, fmaf(a3.z, vr3.z, fmaf(a3.w, vr3.w, p))));
            }
            p += __shfl_xor_sync(0xffffffffu, p, 4);
            p += __shfl_xor_sync(0xffffffffu, p, 2);
            p += __shfl_xor_sync(0xffffffffu, p, 1);
            float s = neg_inf();
            if (valid) {
                float dx = cx[n] - cxc, dy = cy[n] - cyc;
                s = p - 0.1f * sqrtf(dx * dx + dy * dy);
                if (n != 0 && (vis[n] || (dem[n] > rem))) s = neg_inf();
            }
            if (s > best) { best = s; bidx = n; }
        }
        if (j == 0) { red[wid * 4 + g] = best; redi[wid * 4 + g] = bidx; }
        __syncthreads();
        if (wid == 0) {
            float bv = red[lane]; int bi = redi[lane];
            #pragma unroll
            for (int off = 16; off > 0; off >>= 1) {
                float ov = __shfl_xor_sync(0xffffffffu, bv, off);
                int   oi = __shfl_xor_sync(0xffffffffu, bi, off);
                if (ov > bv || (ov == bv && oi < bi)) { bv = ov; bi = oi; }
            }
            if (lane == 0) {
                nxtp[0] = bi;
                vis[bi] = 1;
                out[(size_t)b * T + step] = (float)bi;
            }
        }
        __syncthreads();
        nxt = nxtp[0];
        rem = (nxt == 0) ? cap : (rem - dem[nxt]);
        int prev = cur;
        cur = nxt;
        if (prev == 0 && nxt == 0) break;                  // depot fixed point
    }
}

extern "C" void kernel_launch(void* const* d_in, const int* in_sizes, int n_in,
                              void* d_out, int out_size) {
    const float* x        = (const float*)d_in[0];
    const float* W        = (const float*)d_in[1];
    const float* bias     = (const float*)d_in[2];
    const float* coords   = (const float*)d_in[3];
    const float* demands  = (const float*)d_in[4];
    const float* capacity = (const float*)d_in[5];
    const int*   nsteps   = (n_in > 6) ? (const int*)d_in[6] : nullptr;
    float* out = (float*)d_out;

    k_route<<<BB, 256>>>(x, W, bias, coords, demands, capacity, nsteps, out, out_size);
}